// round 2
// baseline (speedup 1.0000x reference)
#include <cuda_runtime.h>
#include <math.h>

// ---------------- constants ----------------
#define BATCH   4
#define DIM     64
#define HIDDEN  170
#define C2      340           // 2*HIDDEN
#define HW      65536         // 256*256
#define WIDTH   256
#define PP      8
#define PF      5

// ---------------- scratch (device globals; no allocation allowed) ----------------
__device__ float g_xin [(size_t)BATCH * C2 * HW];      // 356 MB
__device__ float g_feat[(size_t)BATCH * HIDDEN * HW];  // 178 MB (feat, then spatial in-place)
__device__ float g_part[BATCH * HIDDEN * 64];          // per-block partial sums for gap
__device__ float g_gap [BATCH * HIDDEN];
__device__ float g_mod [BATCH];

// ---------------- complex helpers ----------------
__device__ __forceinline__ float2 cmul(float2 a, float2 b) {
    return make_float2(a.x * b.x - a.y * b.y, a.x * b.y + a.y * b.x);
}
__device__ __forceinline__ float2 cadd(float2 a, float2 b) { return make_float2(a.x + b.x, a.y + b.y); }
__device__ __forceinline__ float2 csub(float2 a, float2 b) { return make_float2(a.x - b.x, a.y - b.y); }

// in-place complex FFT8, natural order in/out. SIGN=-1 forward (e^{-2pi i nk/8}),
// SIGN=+1 unnormalized inverse.
template <int SIGN>
__device__ __forceinline__ void cfft8(float2 x[8]) {
    float2 e0 = x[0], e1 = x[2], e2 = x[4], e3 = x[6];
    float2 o0 = x[1], o1 = x[3], o2 = x[5], o3 = x[7];
    // fft4 on evens
    float2 t0 = cadd(e0, e2), t1 = csub(e0, e2), t2 = cadd(e1, e3), t3 = csub(e1, e3);
    float2 rt3 = (SIGN < 0) ? make_float2(t3.y, -t3.x) : make_float2(-t3.y, t3.x);
    float2 E0 = cadd(t0, t2), E2 = csub(t0, t2), E1 = cadd(t1, rt3), E3 = csub(t1, rt3);
    // fft4 on odds
    t0 = cadd(o0, o2); t1 = csub(o0, o2); t2 = cadd(o1, o3); t3 = csub(o1, o3);
    rt3 = (SIGN < 0) ? make_float2(t3.y, -t3.x) : make_float2(-t3.y, t3.x);
    float2 O0 = cadd(t0, t2), O2 = csub(t0, t2), O1 = cadd(t1, rt3), O3 = csub(t1, rt3);
    const float s = 0.70710678118654752f;
    const float2 w1 = make_float2(s, (SIGN < 0) ? -s : s);
    const float2 w2 = make_float2(0.f, (SIGN < 0) ? -1.f : 1.f);
    const float2 w3 = make_float2(-s, (SIGN < 0) ? -s : s);
    float2 a;
    a = O0;           x[0] = cadd(E0, a); x[4] = csub(E0, a);
    a = cmul(w1, O1); x[1] = cadd(E1, a); x[5] = csub(E1, a);
    a = cmul(w2, O2); x[2] = cadd(E2, a); x[6] = csub(E2, a);
    a = cmul(w3, O3); x[3] = cadd(E3, a); x[7] = csub(E3, a);
}

// real-input forward FFT8, keep bins 0..4
__device__ __forceinline__ void rfft8(float4 r0, float4 r1, float2 out[5]) {
    float e0 = r0.x, e1 = r0.z, e2 = r1.x, e3 = r1.z;   // v0 v2 v4 v6
    float o0 = r0.y, o1 = r0.w, o2 = r1.y, o3 = r1.w;   // v1 v3 v5 v7
    float ep = e0 + e2, em = e0 - e2, eq = e1 + e3, er = e1 - e3;
    float op = o0 + o2, om = o0 - o2, oq = o1 + o3, orr = o1 - o3;
    float E0 = ep + eq, E2 = ep - eq;
    float O0 = op + oq, O2 = op - oq;
    // E1=(em,-er) E3=(em,er); O1=(om,-orr) O3=(om,orr)
    const float s = 0.70710678118654752f;
    // w1*O1 = (s,-s)*(om,-orr) = (s*(om-orr), s*(-orr-om))
    float w1x = s * (om - orr), w1y = s * (-orr - om);
    // w3*O3 = (-s,-s)*(om,orr) = (s*(orr-om), -s*(om+orr))
    float w3x = s * (orr - om), w3y = -s * (om + orr);
    out[0] = make_float2(E0 + O0, 0.f);
    out[1] = make_float2(em + w1x, -er + w1y);
    out[2] = make_float2(E2, -O2);
    out[3] = make_float2(em + w3x, er + w3y);
    out[4] = make_float2(E0 - O0, 0.f);
}

__device__ __forceinline__ float gelu_exact(float x) {
    return 0.5f * x * (1.f + erff(x * 0.70710678118654752f));
}

// ---------------- K1: x_in = w_in @ x  (340x64 @ 64x65536 per batch) ----------------
__global__ void __launch_bounds__(256) gemm1_kernel(const float* __restrict__ x,
                                                    const float* __restrict__ w_in) {
    __shared__ float Bs[64][128];   // x tile  [c][pos]
    __shared__ float As[64][64];    // w tile transposed [c][o]
    const int b = blockIdx.y;
    const int pos0 = blockIdx.x * 128;
    const int t = threadIdx.x;
    const int pg = t & 31;          // 32 position groups * 4
    const int og = t >> 5;          // 8 o groups * 8

    const float* xb = x + ((size_t)b * 64) * HW + pos0;
#pragma unroll
    for (int i = 0; i < 8; i++) {              // 2048 float4s / 256 threads
        int idx = t + i * 256;
        int cc = idx >> 5, p4 = idx & 31;
        *(float4*)&Bs[cc][p4 * 4] = *(const float4*)(xb + (size_t)cc * HW + p4 * 4);
    }

    for (int ot = 0; ot < 6; ot++) {
        const int ob = ot * 64;
        __syncthreads();
#pragma unroll
        for (int i = 0; i < 16; i++) {         // 4096 / 256
            int idx = t + i * 256;
            int oo = idx >> 6, cc = idx & 63;
            int o = ob + oo;
            As[cc][oo] = (o < C2) ? w_in[o * 64 + cc] : 0.f;
        }
        __syncthreads();

        float4 acc[8];
#pragma unroll
        for (int i = 0; i < 8; i++) acc[i] = make_float4(0.f, 0.f, 0.f, 0.f);

#pragma unroll 8
        for (int cc = 0; cc < 64; cc++) {
            float4 bv = *(const float4*)&Bs[cc][pg * 4];
            const float* ap = &As[cc][og * 8];
#pragma unroll
            for (int i = 0; i < 8; i++) {
                float av = ap[i];
                acc[i].x += av * bv.x; acc[i].y += av * bv.y;
                acc[i].z += av * bv.z; acc[i].w += av * bv.w;
            }
        }
#pragma unroll
        for (int i = 0; i < 8; i++) {
            int o = ob + og * 8 + i;
            if (o < C2)
                *(float4*)&g_xin[((size_t)(b * C2 + o)) * HW + pos0 + pg * 4] = acc[i];
        }
    }
}

// ---------------- K2: depthwise 3x3 + gelu gate + gap partials ----------------
__device__ __forceinline__ float4 conv3x3(const float* __restrict__ base,
                                          const float* __restrict__ wt,
                                          int h, int w0) {
    float k0 = __ldg(wt + 0), k1 = __ldg(wt + 1), k2 = __ldg(wt + 2);
    float k3 = __ldg(wt + 3), k4 = __ldg(wt + 4), k5 = __ldg(wt + 5);
    float k6 = __ldg(wt + 6), k7 = __ldg(wt + 7), k8 = __ldg(wt + 8);
    float ax = 0.f, ay = 0.f, az = 0.f, aw = 0.f;
#pragma unroll
    for (int dy = 0; dy < 3; dy++) {
        int hy = h + dy - 1;
        if (hy < 0 || hy > 255) continue;
        const float* row = base + hy * WIDTH + w0;
        float4 m = *(const float4*)row;
        float lm = (w0 > 0)   ? __ldg(row - 1) : 0.f;
        float rm = (w0 < 252) ? __ldg(row + 4) : 0.f;
        float c0 = (dy == 0) ? k0 : (dy == 1) ? k3 : k6;
        float c1 = (dy == 0) ? k1 : (dy == 1) ? k4 : k7;
        float c2 = (dy == 0) ? k2 : (dy == 1) ? k5 : k8;
        ax += c0 * lm  + c1 * m.x + c2 * m.y;
        ay += c0 * m.x + c1 * m.y + c2 * m.z;
        az += c0 * m.y + c1 * m.z + c2 * m.w;
        aw += c0 * m.z + c1 * m.w + c2 * rm;
    }
    return make_float4(ax, ay, az, aw);
}

__global__ void __launch_bounds__(256) dwk(const float* __restrict__ w_dw) {
    const int bc = blockIdx.z;                 // b*170 + c
    const int b = bc / HIDDEN, c = bc % HIDDEN;
    const int tx = threadIdx.x & 15, ty = threadIdx.x >> 4;
    const int w0 = (blockIdx.x * 16 + tx) * 4; // 0..252
    const int h  = blockIdx.y * 16 + ty;

    const float* base1 = g_xin + ((size_t)(b * C2 + c)) * HW;
    const float* base2 = g_xin + ((size_t)(b * C2 + c + HIDDEN)) * HW;
    float4 a1 = conv3x3(base1, w_dw + c * 9, h, w0);
    float4 a2 = conv3x3(base2, w_dw + (c + HIDDEN) * 9, h, w0);

    float4 f;
    f.x = gelu_exact(a1.x) * a2.x;
    f.y = gelu_exact(a1.y) * a2.y;
    f.z = gelu_exact(a1.z) * a2.z;
    f.w = gelu_exact(a1.w) * a2.w;
    *(float4*)&g_feat[((size_t)bc) * HW + h * WIDTH + w0] = f;

    float s = f.x + f.y + f.z + f.w;
    __shared__ float red[256];
    red[threadIdx.x] = s;
    __syncthreads();
#pragma unroll
    for (int off = 128; off > 0; off >>= 1) {
        if (threadIdx.x < off) red[threadIdx.x] += red[threadIdx.x + off];
        __syncthreads();
    }
    if (threadIdx.x == 0)
        g_part[bc * 64 + blockIdx.y * 4 + blockIdx.x] = red[0];
}

// ---------------- K3a: reduce gap partials (deterministic) ----------------
__global__ void gapred() {
    int i = blockIdx.x * 256 + threadIdx.x;
    if (i < BATCH * HIDDEN) {
        float s = 0.f;
#pragma unroll
        for (int j = 0; j < 64; j++) s += g_part[i * 64 + j];
        g_gap[i] = s;
    }
}

// ---------------- K3b: global modulation scalar per batch ----------------
__global__ void modk(const float* __restrict__ w_mod1, const float* __restrict__ w_mod2) {
    int b = threadIdx.x >> 5, lane = threadIdx.x & 31;
    if (b < BATCH) {
        float m = 0.f;
        for (int j = 0; j < 10; j++) {
            float s = 0.f;
            for (int c = lane; c < HIDDEN; c += 32)
                s += (g_gap[b * HIDDEN + c] * (1.f / 65536.f)) * w_mod1[j * HIDDEN + c];
#pragma unroll
            for (int off = 16; off > 0; off >>= 1) s += __shfl_xor_sync(0xffffffff, s, off);
            m += fmaxf(s, 0.f) * w_mod2[j];
        }
        if (lane == 0) g_mod[b] = 1.f / (1.f + expf(-m));
    }
}

// ---------------- K4: per-patch rfft2 * S -> irfft2 (in place on g_feat) ----------------
__global__ void __launch_bounds__(256) fftk(const float* __restrict__ Wr,
                                            const float* __restrict__ Wi,
                                            const float* __restrict__ csc) {
    const int bc = blockIdx.y;
    const int b = bc / HIDDEN, c = bc % HIDDEN;
    __shared__ float2 S[PP * PF];
    const int t = threadIdx.x;
    if (t < PP * PF) {
        int ky = t / PF, kx = t % PF;
        float mask = expf(-(float)(ky * ky + kx * kx) * (1.f / 18.f));
        float boost = 1.f + mask * (csc[c] * (0.5f + g_mod[b]));
        float sc = boost * (1.f / 64.f);   // fold irfft2 normalization
        S[t] = make_float2(Wr[c * 40 + t] * sc, Wi[c * 40 + t] * sc);
    }
    __syncthreads();

    const int p = blockIdx.x * 256 + t;            // 0..1023 patch id
    float* base = g_feat + (((size_t)bc) << 16) + (p >> 5) * (PP * WIDTH) + (p & 31) * PP;

    float2 F[5][8];                                // F[kx][y] then F[kx][ky]
#pragma unroll
    for (int y = 0; y < 8; y++) {
        float4 r0 = *(const float4*)(base + y * WIDTH);
        float4 r1 = *(const float4*)(base + y * WIDTH + 4);
        float2 o5[5];
        rfft8(r0, r1, o5);
#pragma unroll
        for (int k = 0; k < 5; k++) F[k][y] = o5[k];
    }
#pragma unroll
    for (int k = 0; k < 5; k++) cfft8<-1>(F[k]);   // forward along y
#pragma unroll
    for (int k = 0; k < 5; k++)
#pragma unroll
        for (int ky = 0; ky < 8; ky++)
            F[k][ky] = cmul(F[k][ky], S[ky * PF + k]);
#pragma unroll
    for (int k = 0; k < 5; k++) cfft8<1>(F[k]);    // inverse along y (unnormalized)
#pragma unroll
    for (int y = 0; y < 8; y++) {
        // irfft along x: C2R drops imag of bins 0 and 4 (matches numpy/jnp irfft)
        float2 z[8];
        z[0] = make_float2(F[0][y].x, 0.f);
        z[1] = F[1][y]; z[2] = F[2][y]; z[3] = F[3][y];
        z[4] = make_float2(F[4][y].x, 0.f);
        z[5] = make_float2(F[3][y].x, -F[3][y].y);
        z[6] = make_float2(F[2][y].x, -F[2][y].y);
        z[7] = make_float2(F[1][y].x, -F[1][y].y);
        cfft8<1>(z);
        *(float4*)(base + y * WIDTH)     = make_float4(z[0].x, z[1].x, z[2].x, z[3].x);
        *(float4*)(base + y * WIDTH + 4) = make_float4(z[4].x, z[5].x, z[6].x, z[7].x);
    }
}

// ---------------- K5: out = w_out @ spatial  (64x170 @ 170x65536 per batch) ----------------
__global__ void __launch_bounds__(256) gemm2_kernel(const float* __restrict__ w_out,
                                                    float* __restrict__ out) {
    __shared__ float Bs[34][128];
    __shared__ float As[34][64];   // [c][o]
    const int b = blockIdx.y;
    const int pos0 = blockIdx.x * 128;
    const int t = threadIdx.x;
    const int pg = t & 31, og = t >> 5;

    float4 acc[8];
#pragma unroll
    for (int i = 0; i < 8; i++) acc[i] = make_float4(0.f, 0.f, 0.f, 0.f);

    for (int kc = 0; kc < 5; kc++) {
        const int c0 = kc * 34;
        __syncthreads();
        for (int idx = t; idx < 34 * 32; idx += 256) {          // 1088 float4s
            int cc = idx >> 5, p4 = idx & 31;
            *(float4*)&Bs[cc][p4 * 4] =
                *(const float4*)&g_feat[((size_t)(b * HIDDEN + c0 + cc)) * HW + pos0 + p4 * 4];
        }
        for (int idx = t; idx < 34 * 64; idx += 256) {
            int cc = idx % 34, oo = idx / 34;
            As[cc][oo] = w_out[oo * HIDDEN + c0 + cc];
        }
        __syncthreads();
#pragma unroll 2
        for (int cc = 0; cc < 34; cc++) {
            float4 bv = *(const float4*)&Bs[cc][pg * 4];
            const float* ap = &As[cc][og * 8];
#pragma unroll
            for (int i = 0; i < 8; i++) {
                float av = ap[i];
                acc[i].x += av * bv.x; acc[i].y += av * bv.y;
                acc[i].z += av * bv.z; acc[i].w += av * bv.w;
            }
        }
    }
#pragma unroll
    for (int i = 0; i < 8; i++) {
        int o = og * 8 + i;
        *(float4*)&out[((size_t)(b * 64 + o)) * HW + pos0 + pg * 4] = acc[i];
    }
}

// ---------------- launch ----------------
extern "C" void kernel_launch(void* const* d_in, const int* in_sizes, int n_in,
                              void* d_out, int out_size) {
    const float* x     = (const float*)d_in[0];
    const float* w_in  = (const float*)d_in[1];
    const float* w_dw  = (const float*)d_in[2];
    const float* w_out = (const float*)d_in[3];
    const float* Wr    = (const float*)d_in[4];
    const float* Wi    = (const float*)d_in[5];
    const float* csc   = (const float*)d_in[6];
    const float* wm1   = (const float*)d_in[7];
    const float* wm2   = (const float*)d_in[8];
    float* out = (float*)d_out;

    gemm1_kernel<<<dim3(512, BATCH), 256>>>(x, w_in);
    dwk<<<dim3(4, 16, BATCH * HIDDEN), 256>>>(w_dw);
    gapred<<<3, 256>>>();
    modk<<<1, 128>>>(wm1, wm2);
    fftk<<<dim3(4, BATCH * HIDDEN), 256>>>(Wr, Wi, csc);
    gemm2_kernel<<<dim3(512, BATCH), 256>>>(w_out, out);
}